// round 5
// baseline (speedup 1.0000x reference)
#include <cuda_runtime.h>
#include <cstdint>

// MXFP8 E4M3 quantize->dequantize, 32-element blocks along last axis.
// R4: back to the R2 operating point (4 front-batched LDG.128, occ>=80%),
// but with 8-consecutive-floats-per-thread ownership so one MX block spans
// only 4 lanes -> 2 SHFLs per 8 elements (was 3 per 4). Cuts the warp's
// serial shuffle chain 3x to hide DRAM latency better at high occupancy.
//
// Loads are 32B-strided LDG.128 pairs (each instr takes half of every 32B
// sector, its partner the other half): DRAM sector efficiency unchanged,
// ~2x L1 load wavefronts (L1 has headroom at 43%).
//
// All scales are exact powers of two built by bit manipulation, so every
// multiply matches the reference's fp32 divide bit-for-bit.

static constexpr int EMAX = 8;           // e4m3
static constexpr float MAX_NORM = 448.0f;

__device__ __forceinline__ float quant_e4m3(float x, float iscale, float scale) {
    float a = x * iscale;                          // exact (iscale = 2^k)
    uint32_t au = __float_as_uint(a);
    uint32_t ab = au & 0x7fffffffu;                // |a|
    int pe = (int)(ab >> 23) - 127;                // floor(log2|a|), exact for normals
    pe = max(pe, -6);                              // MIN_EXP (denorm region clamp)
    // lshift = 2^(3-pe), inv_lshift = 2^(pe-3); pe in [-6, 8] -> both normal
    float lsh  = __uint_as_float((uint32_t)(130 - pe) << 23);
    float ilsh = __uint_as_float((uint32_t)(124 + pe) << 23);
    // round-half-away-from-zero on magnitude: product is exact, +0.5 rounds once
    float r = floorf(__uint_as_float(ab) * lsh + 0.5f);
    float m = fminf(r * ilsh, MAX_NORM);           // saturate to e4m3 max normal
    float res = m * scale;
    return __uint_as_float(__float_as_uint(res) | (au & 0x80000000u));
}

// Process 8 consecutive floats (one thread's share of an MX block that spans
// 4 adjacent lanes). Reduction over 4 lanes: xor 1, xor 2.
__device__ __forceinline__ void process8(float4& a, float4& b) {
    float ax = fmaxf(fmaxf(fabsf(a.x), fabsf(a.y)), fmaxf(fabsf(a.z), fabsf(a.w)));
    float bx = fmaxf(fmaxf(fabsf(b.x), fabsf(b.y)), fmaxf(fabsf(b.z), fabsf(b.w)));
    float m = fmaxf(ax, bx);
    m = fmaxf(m, __shfl_xor_sync(0xffffffffu, m, 1));
    m = fmaxf(m, __shfl_xor_sync(0xffffffffu, m, 2));

    int e = (int)(__float_as_uint(m) >> 23);       // m >= 0, no sign bit
    int se = e - 127 - EMAX;
    se = max(se, -127);
    float scale  = __uint_as_float((uint32_t)(se + 127) << 23);
    float iscale = __uint_as_float((uint32_t)(127 - se) << 23);

    a.x = quant_e4m3(a.x, iscale, scale);
    a.y = quant_e4m3(a.y, iscale, scale);
    a.z = quant_e4m3(a.z, iscale, scale);
    a.w = quant_e4m3(a.w, iscale, scale);
    b.x = quant_e4m3(b.x, iscale, scale);
    b.y = quant_e4m3(b.y, iscale, scale);
    b.z = quant_e4m3(b.z, iscale, scale);
    b.w = quant_e4m3(b.w, iscale, scale);
}

__global__ void __launch_bounds__(256) mxq_kernel(const float4* __restrict__ in,
                                                  float4* __restrict__ out,
                                                  int stride2) {
    int g = blockIdx.x * blockDim.x + threadIdx.x;
    int base = 2 * g;                              // two consecutive float4s

    // Front-batched independent loads (MLP_p1 = 4): two streams,
    // 8 consecutive floats each.
    float4 a0 = __ldcs(&in[base]);
    float4 a1 = __ldcs(&in[base + 1]);
    float4 b0 = __ldcs(&in[base + stride2]);
    float4 b1 = __ldcs(&in[base + stride2 + 1]);

    process8(a0, a1);
    process8(b0, b1);

    __stcs(&out[base], a0);
    __stcs(&out[base + 1], a1);
    __stcs(&out[base + stride2], b0);
    __stcs(&out[base + stride2 + 1], b1);
}

extern "C" void kernel_launch(void* const* d_in, const int* in_sizes, int n_in,
                              void* d_out, int out_size) {
    const float4* in = (const float4*)d_in[0];
    float4* out = (float4*)d_out;
    int n4 = out_size / 4;                         // 16,777,216 float4s
    int threads = 256;
    int total_threads = n4 / 4;                    // 4 float4s per thread
    int blocks = total_threads / threads;          // 16384
    int stride2 = 2 * total_threads;               // float4 gap between streams
    mxq_kernel<<<blocks, threads>>>(in, out, stride2);
}